// round 1
// baseline (speedup 1.0000x reference)
#include <cuda_runtime.h>
#include <cuda_bf16.h>

// ---------------------------------------------------------------------------
// MQA block: B=2, S=2048, H=4096, NH=32, D=128 (single shared KV head)
// fp32 throughout this round (accuracy anchor). All GEMMs share one NT kernel.
// ---------------------------------------------------------------------------

#define Bb 2
#define Ss 2048
#define Hh 4096
#define NHh 32
#define Dd 128

// Scratch (static __device__ — allocation-free per harness rules)
__device__ float g_Q [4096u * 4096u];           // (B*S, H)      64 MB
__device__ float g_K [2u * 2048u * 128u];       // (B, S, D)      2 MB
__device__ float g_V [2u * 2048u * 128u];       //                2 MB
__device__ float g_VT[2u * 128u * 2048u];       // (B, D, S)      2 MB
__device__ float g_S [268435456u];              // (64, S, S)     1 GB
__device__ float g_O [64u * 2048u * 128u];      // (B*NH, S, D)  64 MB
__device__ float g_X [2u * 2048u * 4096u];      // scrambled     64 MB

// ---------------------------------------------------------------------------
// Generic NT SGEMM: C[m,n] = alpha * sum_k A[m,k]*B[n,k] + bias[n]
// Tile 128x128x16, 256 threads, 8x8 per-thread microtile, double-buffered smem.
// Requires M%128==0, N%128==0, K%16==0, pointers/lds 16B-aligned (all true here).
// Batch z offset: (z/zdiv)*s?hi + (z%zdiv)*s?lo
// ---------------------------------------------------------------------------
__global__ __launch_bounds__(256, 2)
void sgemm_nt(const float* __restrict__ Ag, const float* __restrict__ Bg,
              float* __restrict__ Cg, const float* __restrict__ bias,
              int M, int N, int K, int lda, int ldb, int ldc, int zdiv,
              long long sAhi, long long sAlo, long long sBhi, long long sBlo,
              long long sChi, long long sClo, float alpha)
{
    const int z  = blockIdx.z;
    const int zh = z / zdiv, zl = z % zdiv;
    const float* A = Ag + zh * sAhi + zl * sAlo;
    const float* B = Bg + zh * sBhi + zl * sBlo;
    float*       C = Cg + zh * sChi + zl * sClo;

    __shared__ float As[2][16][132];
    __shared__ float Bs[2][16][132];

    const int tid = threadIdx.x;
    const int tx  = tid & 15;    // n-direction
    const int ty  = tid >> 4;    // m-direction
    const int bm  = blockIdx.y << 7;
    const int bn  = blockIdx.x << 7;

    const int lr = tid >> 2;         // 0..63 (tile row)
    const int lc = (tid & 3) << 2;   // 0,4,8,12 (k col)

    const float* Ap = A + (long long)(bm + lr) * lda + lc;
    const float* Bp = B + (long long)(bn + lr) * ldb + lc;
    const long long ldA64 = (long long)lda * 64;
    const long long ldB64 = (long long)ldb * 64;

    float bj[8];
#pragma unroll
    for (int j = 0; j < 8; ++j)
        bj[j] = bias ? __ldg(&bias[bn + tx * 8 + j]) : 0.0f;

    float4 a0 = *(const float4*)(Ap);
    float4 a1 = *(const float4*)(Ap + ldA64);
    float4 b0 = *(const float4*)(Bp);
    float4 b1 = *(const float4*)(Bp + ldB64);

    float acc[8][8];
#pragma unroll
    for (int i = 0; i < 8; ++i)
#pragma unroll
        for (int j = 0; j < 8; ++j) acc[i][j] = 0.0f;

    const int nk = K >> 4;

#define STORE_TILE(s)                                                              \
    do {                                                                           \
        As[s][lc+0][lr]    = a0.x; As[s][lc+1][lr]    = a0.y;                      \
        As[s][lc+2][lr]    = a0.z; As[s][lc+3][lr]    = a0.w;                      \
        As[s][lc+0][lr+64] = a1.x; As[s][lc+1][lr+64] = a1.y;                      \
        As[s][lc+2][lr+64] = a1.z; As[s][lc+3][lr+64] = a1.w;                      \
        Bs[s][lc+0][lr]    = b0.x; Bs[s][lc+1][lr]    = b0.y;                      \
        Bs[s][lc+2][lr]    = b0.z; Bs[s][lc+3][lr]    = b0.w;                      \
        Bs[s][lc+0][lr+64] = b1.x; Bs[s][lc+1][lr+64] = b1.y;                      \
        Bs[s][lc+2][lr+64] = b1.z; Bs[s][lc+3][lr+64] = b1.w;                      \
    } while (0)

    STORE_TILE(0);
    __syncthreads();

    for (int kt = 0; kt < nk; ++kt) {
        const int st = kt & 1;
        if (kt + 1 < nk) {
            const float* Ap2 = Ap + (kt + 1) * 16;
            const float* Bp2 = Bp + (kt + 1) * 16;
            a0 = *(const float4*)(Ap2);
            a1 = *(const float4*)(Ap2 + ldA64);
            b0 = *(const float4*)(Bp2);
            b1 = *(const float4*)(Bp2 + ldB64);
        }
#pragma unroll
        for (int k = 0; k < 16; ++k) {
            float4 av0 = *(const float4*)&As[st][k][ty * 8];
            float4 av1 = *(const float4*)&As[st][k][ty * 8 + 4];
            float4 bv0 = *(const float4*)&Bs[st][k][tx * 8];
            float4 bv1 = *(const float4*)&Bs[st][k][tx * 8 + 4];
            float a[8] = {av0.x, av0.y, av0.z, av0.w, av1.x, av1.y, av1.z, av1.w};
            float b[8] = {bv0.x, bv0.y, bv0.z, bv0.w, bv1.x, bv1.y, bv1.z, bv1.w};
#pragma unroll
            for (int i = 0; i < 8; ++i)
#pragma unroll
                for (int j = 0; j < 8; ++j)
                    acc[i][j] = fmaf(a[i], b[j], acc[i][j]);
        }
        if (kt + 1 < nk) {
            const int s2 = (kt + 1) & 1;
            STORE_TILE(s2);
        }
        __syncthreads();
    }

#pragma unroll
    for (int i = 0; i < 8; ++i) {
        float* Crow = C + (long long)(bm + ty * 8 + i) * ldc + bn + tx * 8;
        float4 o0 = make_float4(fmaf(alpha, acc[i][0], bj[0]),
                                fmaf(alpha, acc[i][1], bj[1]),
                                fmaf(alpha, acc[i][2], bj[2]),
                                fmaf(alpha, acc[i][3], bj[3]));
        float4 o1 = make_float4(fmaf(alpha, acc[i][4], bj[4]),
                                fmaf(alpha, acc[i][5], bj[5]),
                                fmaf(alpha, acc[i][6], bj[6]),
                                fmaf(alpha, acc[i][7], bj[7]));
        *(float4*)(Crow)     = o0;
        *(float4*)(Crow + 4) = o1;
    }
#undef STORE_TILE
}

// ---------------------------------------------------------------------------
// Row softmax over 2048-wide rows. One block (256 thr) per row, 8 elems/thread.
// ---------------------------------------------------------------------------
__global__ __launch_bounds__(256)
void softmax_rows(float* __restrict__ Sm)
{
    float* row = Sm + (long long)blockIdx.x * 2048;
    const int tid = threadIdx.x;
    float4 v0 = ((float4*)row)[tid];
    float4 v1 = ((float4*)row)[tid + 256];

    float m = fmaxf(fmaxf(fmaxf(v0.x, v0.y), fmaxf(v0.z, v0.w)),
                    fmaxf(fmaxf(v1.x, v1.y), fmaxf(v1.z, v1.w)));
#pragma unroll
    for (int o = 16; o > 0; o >>= 1)
        m = fmaxf(m, __shfl_xor_sync(0xffffffffu, m, o));

    __shared__ float redm[8];
    __shared__ float reds[8];
    if ((tid & 31) == 0) redm[tid >> 5] = m;
    __syncthreads();
    float mm = redm[0];
#pragma unroll
    for (int i = 1; i < 8; ++i) mm = fmaxf(mm, redm[i]);

    v0.x = __expf(v0.x - mm); v0.y = __expf(v0.y - mm);
    v0.z = __expf(v0.z - mm); v0.w = __expf(v0.w - mm);
    v1.x = __expf(v1.x - mm); v1.y = __expf(v1.y - mm);
    v1.z = __expf(v1.z - mm); v1.w = __expf(v1.w - mm);

    float s = v0.x + v0.y + v0.z + v0.w + v1.x + v1.y + v1.z + v1.w;
#pragma unroll
    for (int o = 16; o > 0; o >>= 1)
        s += __shfl_xor_sync(0xffffffffu, s, o);
    if ((tid & 31) == 0) reds[tid >> 5] = s;
    __syncthreads();
    float tot = 0.0f;
#pragma unroll
    for (int i = 0; i < 8; ++i) tot += reds[i];
    const float inv = 1.0f / tot;

    v0.x *= inv; v0.y *= inv; v0.z *= inv; v0.w *= inv;
    v1.x *= inv; v1.y *= inv; v1.z *= inv; v1.w *= inv;
    ((float4*)row)[tid]       = v0;
    ((float4*)row)[tid + 256] = v1;
}

// V (B,S,D) -> VT (B,D,S)
__global__ void transpose_v(const float* __restrict__ v, float* __restrict__ vt)
{
    long long i = (long long)blockIdx.x * blockDim.x + threadIdx.x;
    if (i < 2LL * 2048 * 128) {
        int d = (int)(i & 127);
        int t = (int)((i >> 7) & 2047);
        int b = (int)(i >> 18);
        vt[((long long)b * 128 + d) * 2048 + t] = v[i];
    }
}

// O (b,h,s,d) -> X[b, h*64 + d/2, (d&1)*2048 + s]  (= swapaxes(-1,-2).reshape)
__global__ void permute_o(const float* __restrict__ O, float* __restrict__ X)
{
    long long i = (long long)blockIdx.x * blockDim.x + threadIdx.x;
    if (i < 64LL * 2048 * 128) {
        int dd = (int)(i & 127);
        int ss = (int)((i >> 7) & 2047);
        int h  = (int)((i >> 18) & 31);
        int b  = (int)(i >> 23);
        int r  = h * 64 + (dd >> 1);
        int c  = (dd & 1) * 2048 + ss;
        X[((long long)(b * 2048 + r)) * 4096 + c] = O[i];
    }
}

extern "C" void kernel_launch(void* const* d_in, const int* in_sizes, int n_in,
                              void* d_out, int out_size)
{
    const float* hs = (const float*)d_in[0];
    const float* Wq = (const float*)d_in[1];
    const float* bq = (const float*)d_in[2];
    const float* Wk = (const float*)d_in[3];
    const float* bk = (const float*)d_in[4];
    const float* Wv = (const float*)d_in[5];
    const float* bv = (const float*)d_in[6];
    const float* Wo = (const float*)d_in[7];
    const float* bo = (const float*)d_in[8];
    float* out = (float*)d_out;

    float *pQ, *pK, *pV, *pVT, *pS, *pO, *pX;
    cudaGetSymbolAddress((void**)&pQ,  g_Q);
    cudaGetSymbolAddress((void**)&pK,  g_K);
    cudaGetSymbolAddress((void**)&pV,  g_V);
    cudaGetSymbolAddress((void**)&pVT, g_VT);
    cudaGetSymbolAddress((void**)&pS,  g_S);
    cudaGetSymbolAddress((void**)&pO,  g_O);
    cudaGetSymbolAddress((void**)&pX,  g_X);

    const float scale = 0.08838834764831845f;  // 1/sqrt(128)

    // Q = hs @ Wq^T + bq   (4096 x 4096 x 4096)
    sgemm_nt<<<dim3(32, 32, 1), 256>>>(hs, Wq, pQ, bq,
        4096, 4096, 4096, 4096, 4096, 4096, 1, 0, 0, 0, 0, 0, 0, 1.0f);

    // K = hs @ Wk^T + bk   (4096 x 128 x 4096)
    sgemm_nt<<<dim3(1, 32, 1), 256>>>(hs, Wk, pK, bk,
        4096, 128, 4096, 4096, 4096, 128, 1, 0, 0, 0, 0, 0, 0, 1.0f);

    // V = hs @ Wv^T + bv
    sgemm_nt<<<dim3(1, 32, 1), 256>>>(hs, Wv, pV, bv,
        4096, 128, 4096, 4096, 4096, 128, 1, 0, 0, 0, 0, 0, 0, 1.0f);

    // VT (B,D,S)
    transpose_v<<<2048, 256>>>(pV, pVT);

    // scores[z=b*32+h] = scale * Q_slice @ K_b^T   (2048 x 2048 x 128, 64 batches)
    sgemm_nt<<<dim3(16, 16, 64), 256>>>(pQ, pK, pS, nullptr,
        2048, 2048, 128, 4096, 128, 2048, 32,
        /*A*/ 2048LL * 4096, 128LL,
        /*B*/ 2048LL * 128, 0LL,
        /*C*/ 32LL * 2048 * 2048, 2048LL * 2048, scale);

    // softmax over last dim (64*2048 rows)
    softmax_rows<<<64 * 2048, 256>>>(pS);

    // O[z] = P[z] @ VT_b^T   (2048 x 128 x 2048, 64 batches)
    sgemm_nt<<<dim3(1, 16, 64), 256>>>(pS, pVT, pO, nullptr,
        2048, 128, 2048, 2048, 2048, 128, 32,
        /*A*/ 32LL * 2048 * 2048, 2048LL * 2048,
        /*B*/ 128LL * 2048, 0LL,
        /*C*/ 32LL * 2048 * 128, 2048LL * 128, 1.0f);

    // scrambled reshape
    permute_o<<<65536, 256>>>(pO, pX);

    // out = X @ Wo^T + bo   (4096 x 4096 x 4096)
    sgemm_nt<<<dim3(32, 32, 1), 256>>>(pX, Wo, out, bo,
        4096, 4096, 4096, 4096, 4096, 4096, 1, 0, 0, 0, 0, 0, 0, 1.0f);
}

// round 3
// speedup vs baseline: 1.6915x; 1.6915x over previous
#include <cuda_runtime.h>
#include <cuda_bf16.h>
#include <cstdint>

typedef __nv_bfloat16 bf16;

// ===========================================================================
// MQA block: B=2, S=2048, H=4096, NH=32, D=128.
// GEMMs: mma.sync.m16n8k16 bf16 split-precision (hi/lo, 3 passes), fp32 accum.
// (tcgen05 unusable: harness PTX target is sm_103 base arch.)
// ===========================================================================

// ---------------- scratch ----------------
__device__ __align__(16) bf16 g_hs_hi[16777216], g_hs_lo[16777216];
__device__ __align__(16) bf16 g_Wq_hi[16777216], g_Wq_lo[16777216];
__device__ __align__(16) bf16 g_Wk_hi[524288],  g_Wk_lo[524288];
__device__ __align__(16) bf16 g_Wv_hi[524288],  g_Wv_lo[524288];
__device__ __align__(16) bf16 g_Wo_hi[16777216], g_Wo_lo[16777216];
__device__ __align__(16) bf16 g_Q_hi[16777216],  g_Q_lo[16777216];
__device__ __align__(16) bf16 g_K_hi[524288],   g_K_lo[524288];
__device__ __align__(16) bf16 g_V_hi[524288],   g_V_lo[524288];
__device__ __align__(16) bf16 g_VT_hi[524288],  g_VT_lo[524288];
__device__ __align__(16) float g_S[268435456];                   // (64,2048,2048)
__device__ __align__(16) bf16 g_P_hi[268435456], g_P_lo[268435456];
__device__ __align__(16) float g_O[16777216];                    // (64,2048,128)
__device__ __align__(16) bf16 g_X_hi[16777216],  g_X_lo[16777216];

// ---------------- PTX helpers ----------------
__device__ __forceinline__ uint32_t s2u(const void* p) {
    uint32_t a;
    asm("{ .reg .u64 t; cvta.to.shared.u64 t, %1; cvt.u32.u64 %0, t; }" : "=r"(a) : "l"(p));
    return a;
}
#define CP16(dst, src) \
    asm volatile("cp.async.cg.shared.global [%0], [%1], 16;" :: "r"(dst), "l"(src))
#define CP_COMMIT() asm volatile("cp.async.commit_group;" ::: "memory")
#define CP_WAIT(n)  asm volatile("cp.async.wait_group %0;" :: "n"(n) : "memory")

#define LDSM4(r0, r1, r2, r3, a) \
    asm volatile("ldmatrix.sync.aligned.m8n8.x4.shared.b16 {%0,%1,%2,%3}, [%4];" \
                 : "=r"(r0), "=r"(r1), "=r"(r2), "=r"(r3) : "r"(a))

#define MMA16816(d, a, b) \
    asm volatile("mma.sync.aligned.m16n8k16.row.col.f32.bf16.bf16.f32 " \
                 "{%0,%1,%2,%3}, {%4,%5,%6,%7}, {%8,%9}, {%0,%1,%2,%3};" \
                 : "+f"((d)[0]), "+f"((d)[1]), "+f"((d)[2]), "+f"((d)[3]) \
                 : "r"((a)[0]), "r"((a)[1]), "r"((a)[2]), "r"((a)[3]), \
                   "r"((b)[0]), "r"((b)[1]))

// smem tile: rows of 32 bf16 (64B), 16B chunks XOR-swizzled by (row & 3)
__device__ __forceinline__ uint32_t swz(uint32_t row, uint32_t chunk) {
    return row * 64u + ((chunk ^ (row & 3u)) << 4);
}

#define NSTAGE 4
#define STAGE_BYTES 16384          // A 8KB + B 8KB
#define SMEM_TOTAL (NSTAGE * STAGE_BYTES)

// ===========================================================================
// Split-bf16 NT GEMM: C = alpha*(Ah@Bh^T + Ah@Bl^T + Al@Bh^T) + bias
// Tile 128x128x32, 256 threads, warp tile 64x32. Batched via z.
// ===========================================================================
__global__ __launch_bounds__(256)
void gemm_split(const bf16* __restrict__ Ahi, const bf16* __restrict__ Alo,
                const bf16* __restrict__ Bhi, const bf16* __restrict__ Blo,
                float* __restrict__ Cf, bf16* __restrict__ Chi, bf16* __restrict__ Clo,
                const float* __restrict__ bias,
                int K, int lda, int ldb, int ldc, int zdiv,
                long long zAh, long long zAl, long long zBh, long long zBl,
                long long zCh, long long zCl, float alpha)
{
    extern __shared__ __align__(1024) char smem[];
    const uint32_t sb = s2u(smem);
    const int tid = threadIdx.x;
    const int wid = tid >> 5, lane = tid & 31;
    const int wm = wid & 1, wn = wid >> 1;       // 2 x 4 warp grid

    const int z = blockIdx.z, zh = z / zdiv, zl = z % zdiv;
    const bf16* A0 = Ahi + zh * zAh + zl * zAl;
    const bf16* A1 = Alo + zh * zAh + zl * zAl;
    const bf16* B0 = Bhi + zh * zBh + zl * zBl;
    const bf16* B1 = Blo + zh * zBh + zl * zBl;
    const long long coff = zh * zCh + zl * zCl;
    const int bm = blockIdx.y << 7, bn = blockIdx.x << 7;

    const int nk = K >> 5;          // k-chunks of 32
    const int T  = 3 * nk;          // hi*hi, hi*lo, lo*hi

    // loader mapping: thread t -> row t>>1 (0..127), chunks (t&1)*2 + {0,1}
    const int lrow = tid >> 1;
    const int lkc  = (tid & 1) * 2;

    auto issue_loads = [&](int c, int s) {
        const int p  = c / nk;
        const int kk = c - p * nk;
        const bf16* Ab = (p == 2) ? A1 : A0;
        const bf16* Bb = (p == 1) ? B1 : B0;
        const bf16* ag = Ab + (long long)(bm + lrow) * lda + kk * 32 + lkc * 8;
        const bf16* bg = Bb + (long long)(bn + lrow) * ldb + kk * 32 + lkc * 8;
        const uint32_t abase = sb + s * STAGE_BYTES;
        const uint32_t bbase = abase + 8192;
        CP16(abase + swz(lrow, lkc),     ag);
        CP16(abase + swz(lrow, lkc + 1), ag + 8);
        CP16(bbase + swz(lrow, lkc),     bg);
        CP16(bbase + swz(lrow, lkc + 1), bg + 8);
    };

    float acc[4][4][4];
#pragma unroll
    for (int i = 0; i < 4; ++i)
#pragma unroll
        for (int j = 0; j < 4; ++j)
#pragma unroll
            for (int r = 0; r < 4; ++r) acc[i][j][r] = 0.0f;

#pragma unroll
    for (int s = 0; s < NSTAGE - 1; ++s) { issue_loads(s, s); CP_COMMIT(); }

    const int l15 = lane & 15;
    const int lhi = lane >> 4;

    for (int i = 0; i < T; ++i) {
        const int st = i & (NSTAGE - 1);
        CP_WAIT(NSTAGE - 2);
        __syncthreads();

        // prefetch chunk i+NSTAGE-1 into stage (i-1)%NSTAGE
        if (i + NSTAGE - 1 < T) issue_loads(i + NSTAGE - 1, (i + NSTAGE - 1) & (NSTAGE - 1));
        CP_COMMIT();

        const uint32_t abase = sb + st * STAGE_BYTES;
        const uint32_t bbase = abase + 8192;

#pragma unroll
        for (int kk = 0; kk < 2; ++kk) {
            uint32_t af[4][4], bf[4][2];
#pragma unroll
            for (int mi = 0; mi < 4; ++mi) {
                const uint32_t row = wm * 64 + mi * 16 + l15;
                LDSM4(af[mi][0], af[mi][1], af[mi][2], af[mi][3],
                      abase + swz(row, kk * 2 + lhi));
            }
#pragma unroll
            for (int jj = 0; jj < 2; ++jj) {
                uint32_t r0, r1, r2, r3;
                const uint32_t row = wn * 32 + jj * 16 + l15;
                LDSM4(r0, r1, r2, r3, bbase + swz(row, kk * 2 + lhi));
                bf[jj * 2][0] = r0;     bf[jj * 2][1] = r2;
                bf[jj * 2 + 1][0] = r1; bf[jj * 2 + 1][1] = r3;
            }
#pragma unroll
            for (int mi = 0; mi < 4; ++mi)
#pragma unroll
                for (int j = 0; j < 4; ++j)
                    MMA16816(acc[mi][j], af[mi], bf[j]);
        }
    }

    // ---------------- epilogue ----------------
    const int r0 = lane >> 2, c0 = (lane & 3) * 2;
#pragma unroll
    for (int mi = 0; mi < 4; ++mi) {
#pragma unroll
        for (int rr = 0; rr < 2; ++rr) {
            const int m = bm + wm * 64 + mi * 16 + r0 + rr * 8;
            const long long rbase = coff + (long long)m * ldc;
#pragma unroll
            for (int j = 0; j < 4; ++j) {
                const int n = bn + wn * 32 + j * 8 + c0;
                float x0 = alpha * acc[mi][j][rr * 2 + 0];
                float x1 = alpha * acc[mi][j][rr * 2 + 1];
                if (bias) { x0 += __ldg(&bias[n]); x1 += __ldg(&bias[n + 1]); }
                if (Cf) *(float2*)(Cf + rbase + n) = make_float2(x0, x1);
                if (Chi) {
                    bf16 h0 = __float2bfloat16(x0), h1 = __float2bfloat16(x1);
                    bf16 l0 = __float2bfloat16(x0 - __bfloat162float(h0));
                    bf16 l1 = __float2bfloat16(x1 - __bfloat162float(h1));
                    bf16 hp[2] = {h0, h1}, lp[2] = {l0, l1};
                    *(uint32_t*)(Chi + rbase + n) = *(uint32_t*)hp;
                    *(uint32_t*)(Clo + rbase + n) = *(uint32_t*)lp;
                }
            }
        }
    }
}

// ===========================================================================
// elementwise helpers
// ===========================================================================
__global__ __launch_bounds__(256)
void split_fp32(const float* __restrict__ x, bf16* __restrict__ hi, bf16* __restrict__ lo)
{
    long long i = ((long long)blockIdx.x * 256 + threadIdx.x) * 4;
    float4 v = *(const float4*)(x + i);
    bf16 h[4], l[4];
    float a[4] = {v.x, v.y, v.z, v.w};
#pragma unroll
    for (int j = 0; j < 4; ++j) {
        h[j] = __float2bfloat16(a[j]);
        l[j] = __float2bfloat16(a[j] - __bfloat162float(h[j]));
    }
    *(uint2*)(hi + i) = *(uint2*)h;
    *(uint2*)(lo + i) = *(uint2*)l;
}

__global__ __launch_bounds__(256)
void transpose_v_split(const bf16* __restrict__ vh, const bf16* __restrict__ vl,
                       bf16* __restrict__ th, bf16* __restrict__ tl)
{
    long long i = (long long)blockIdx.x * 256 + threadIdx.x;
    int d = (int)(i & 127);
    int t = (int)((i >> 7) & 2047);
    int b = (int)(i >> 18);
    long long o = ((long long)b * 128 + d) * 2048 + t;
    th[o] = vh[i];
    tl[o] = vl[i];
}

__global__ __launch_bounds__(256)
void softmax_split(const float* __restrict__ S, bf16* __restrict__ Ph, bf16* __restrict__ Pl)
{
    const float* row = S + (long long)blockIdx.x * 2048;
    const int tid = threadIdx.x;
    float4 v0 = ((const float4*)row)[tid * 2];
    float4 v1 = ((const float4*)row)[tid * 2 + 1];

    float m = fmaxf(fmaxf(fmaxf(v0.x, v0.y), fmaxf(v0.z, v0.w)),
                    fmaxf(fmaxf(v1.x, v1.y), fmaxf(v1.z, v1.w)));
#pragma unroll
    for (int o = 16; o > 0; o >>= 1) m = fmaxf(m, __shfl_xor_sync(~0u, m, o));
    __shared__ float redm[8], reds[8];
    if ((tid & 31) == 0) redm[tid >> 5] = m;
    __syncthreads();
    float mm = redm[0];
#pragma unroll
    for (int i = 1; i < 8; ++i) mm = fmaxf(mm, redm[i]);

    float e[8] = {__expf(v0.x - mm), __expf(v0.y - mm), __expf(v0.z - mm), __expf(v0.w - mm),
                  __expf(v1.x - mm), __expf(v1.y - mm), __expf(v1.z - mm), __expf(v1.w - mm)};
    float s = e[0] + e[1] + e[2] + e[3] + e[4] + e[5] + e[6] + e[7];
#pragma unroll
    for (int o = 16; o > 0; o >>= 1) s += __shfl_xor_sync(~0u, s, o);
    if ((tid & 31) == 0) reds[tid >> 5] = s;
    __syncthreads();
    float tot = 0.0f;
#pragma unroll
    for (int i = 0; i < 8; ++i) tot += reds[i];
    const float inv = 1.0f / tot;

    bf16 h8[8], l8[8];
#pragma unroll
    for (int j = 0; j < 8; ++j) {
        float p = e[j] * inv;
        bf16 hh = __float2bfloat16(p);
        h8[j] = hh;
        l8[j] = __float2bfloat16(p - __bfloat162float(hh));
    }
    long long base = (long long)blockIdx.x * 2048 + tid * 8;
    *(uint4*)(Ph + base) = *(uint4*)h8;
    *(uint4*)(Pl + base) = *(uint4*)l8;
}

__global__ __launch_bounds__(256)
void permute_o_split(const float* __restrict__ O, bf16* __restrict__ Xh, bf16* __restrict__ Xl)
{
    long long i = (long long)blockIdx.x * 256 + threadIdx.x;
    int dd = (int)(i & 127);
    int ss = (int)((i >> 7) & 2047);
    int h  = (int)((i >> 18) & 31);
    int b  = (int)(i >> 23);
    int r  = h * 64 + (dd >> 1);
    int c  = (dd & 1) * 2048 + ss;
    long long o = ((long long)(b * 2048 + r)) * 4096 + c;
    float x = O[i];
    bf16 hh = __float2bfloat16(x);
    Xh[o] = hh;
    Xl[o] = __float2bfloat16(x - __bfloat162float(hh));
}

// ===========================================================================
extern "C" void kernel_launch(void* const* d_in, const int* in_sizes, int n_in,
                              void* d_out, int out_size)
{
    const float* hs = (const float*)d_in[0];
    const float* Wq = (const float*)d_in[1];
    const float* bq = (const float*)d_in[2];
    const float* Wk = (const float*)d_in[3];
    const float* bk = (const float*)d_in[4];
    const float* Wv = (const float*)d_in[5];
    const float* bv = (const float*)d_in[6];
    const float* Wo = (const float*)d_in[7];
    const float* bo = (const float*)d_in[8];
    float* out = (float*)d_out;

    bf16 *hsh, *hsl, *wqh, *wql, *wkh, *wkl, *wvh, *wvl, *woh, *wol;
    bf16 *qh, *ql, *kh, *kl, *vh, *vl, *vth, *vtl, *ph, *pl, *xh, *xl;
    float *pS, *pO;
    cudaGetSymbolAddress((void**)&hsh, g_hs_hi); cudaGetSymbolAddress((void**)&hsl, g_hs_lo);
    cudaGetSymbolAddress((void**)&wqh, g_Wq_hi); cudaGetSymbolAddress((void**)&wql, g_Wq_lo);
    cudaGetSymbolAddress((void**)&wkh, g_Wk_hi); cudaGetSymbolAddress((void**)&wkl, g_Wk_lo);
    cudaGetSymbolAddress((void**)&wvh, g_Wv_hi); cudaGetSymbolAddress((void**)&wvl, g_Wv_lo);
    cudaGetSymbolAddress((void**)&woh, g_Wo_hi); cudaGetSymbolAddress((void**)&wol, g_Wo_lo);
    cudaGetSymbolAddress((void**)&qh,  g_Q_hi);  cudaGetSymbolAddress((void**)&ql,  g_Q_lo);
    cudaGetSymbolAddress((void**)&kh,  g_K_hi);  cudaGetSymbolAddress((void**)&kl,  g_K_lo);
    cudaGetSymbolAddress((void**)&vh,  g_V_hi);  cudaGetSymbolAddress((void**)&vl,  g_V_lo);
    cudaGetSymbolAddress((void**)&vth, g_VT_hi); cudaGetSymbolAddress((void**)&vtl, g_VT_lo);
    cudaGetSymbolAddress((void**)&ph,  g_P_hi);  cudaGetSymbolAddress((void**)&pl,  g_P_lo);
    cudaGetSymbolAddress((void**)&xh,  g_X_hi);  cudaGetSymbolAddress((void**)&xl,  g_X_lo);
    cudaGetSymbolAddress((void**)&pS,  g_S);     cudaGetSymbolAddress((void**)&pO,  g_O);

    cudaFuncSetAttribute(gemm_split, cudaFuncAttributeMaxDynamicSharedMemorySize, SMEM_TOTAL);

    const float scale = 0.08838834764831845f;  // 1/sqrt(128)

    split_fp32<<<16384, 256>>>(hs, hsh, hsl);
    split_fp32<<<16384, 256>>>(Wq, wqh, wql);
    split_fp32<<<512,   256>>>(Wk, wkh, wkl);
    split_fp32<<<512,   256>>>(Wv, wvh, wvl);
    split_fp32<<<16384, 256>>>(Wo, woh, wol);

    // Q = hs @ Wq^T + bq -> split   (4096 x 4096 x 4096)
    gemm_split<<<dim3(32, 32, 1), 256, SMEM_TOTAL>>>(
        hsh, hsl, wqh, wql, nullptr, qh, ql, bq,
        4096, 4096, 4096, 4096, 1, 0, 0, 0, 0, 0, 0, 1.0f);

    // K, V = hs @ W^T + b -> split  (4096 x 128 x 4096)
    gemm_split<<<dim3(1, 32, 1), 256, SMEM_TOTAL>>>(
        hsh, hsl, wkh, wkl, nullptr, kh, kl, bk,
        4096, 4096, 4096, 128, 1, 0, 0, 0, 0, 0, 0, 1.0f);
    gemm_split<<<dim3(1, 32, 1), 256, SMEM_TOTAL>>>(
        hsh, hsl, wvh, wvl, nullptr, vh, vl, bv,
        4096, 4096, 4096, 128, 1, 0, 0, 0, 0, 0, 0, 1.0f);

    transpose_v_split<<<2048, 256>>>(vh, vl, vth, vtl);

    // S[z] = scale * Q_slice @ K_b^T  (2048 x 2048 x 128, 64 batches)
    gemm_split<<<dim3(16, 16, 64), 256, SMEM_TOTAL>>>(
        qh, ql, kh, kl, pS, nullptr, nullptr, nullptr,
        128, 4096, 128, 2048, 32,
        2048LL * 4096, 128LL, 2048LL * 128, 0LL,
        32LL * 2048 * 2048, 2048LL * 2048, scale);

    softmax_split<<<64 * 2048, 256>>>(pS, ph, pl);

    // O[z] = P[z] @ VT_b^T            (2048 x 128 x 2048, 64 batches)
    gemm_split<<<dim3(1, 16, 64), 256, SMEM_TOTAL>>>(
        ph, pl, vth, vtl, pO, nullptr, nullptr, nullptr,
        2048, 2048, 2048, 128, 32,
        32LL * 2048 * 2048, 2048LL * 2048, 128LL * 2048, 0LL,
        32LL * 2048 * 128, 2048LL * 128, 1.0f);

    permute_o_split<<<65536, 256>>>(pO, xh, xl);

    // out = X @ Wo^T + bo             (4096 x 4096 x 4096)
    gemm_split<<<dim3(32, 32, 1), 256, SMEM_TOTAL>>>(
        xh, xl, woh, wol, out, nullptr, nullptr, bo,
        4096, 4096, 4096, 4096, 1, 0, 0, 0, 0, 0, 0, 1.0f);
}

// round 5
// speedup vs baseline: 1.8117x; 1.0710x over previous
#include <cuda_runtime.h>
#include <cuda_bf16.h>
#include <cstdint>

typedef __nv_bfloat16 bf16;

// ===========================================================================
// MQA block: B=2, S=2048, H=4096, NH=32, D=128.
// GEMMs: mma.sync.m16n8k16 bf16 split-precision (hi/lo, 3 passes), fp32 accum.
// Round 4: Q/K/V fused into ONE projection GEMM (N=4352) so the KV columns
// fill wave slack instead of running on 32/148 SMs.
// ===========================================================================

// ---------------- scratch ----------------
__device__ __align__(16) bf16 g_hs_hi[16777216], g_hs_lo[16777216];
__device__ __align__(16) bf16 g_Wc_hi[17825792], g_Wc_lo[17825792];   // [4352][4096]
__device__ __align__(16) float g_bc[4352];                            // [bq|bk|bv]
__device__ __align__(16) bf16 g_Wo_hi[16777216], g_Wo_lo[16777216];
__device__ __align__(16) bf16 g_QKV_hi[17825792], g_QKV_lo[17825792]; // [4096][4352]
__device__ __align__(16) bf16 g_VT_hi[524288],  g_VT_lo[524288];      // (B,D,S)
__device__ __align__(16) float g_S[268435456];                        // (64,2048,2048)
__device__ __align__(16) bf16 g_P_hi[268435456], g_P_lo[268435456];
__device__ __align__(16) float g_O[16777216];                         // (64,2048,128)
__device__ __align__(16) bf16 g_X_hi[16777216],  g_X_lo[16777216];

// ---------------- PTX helpers ----------------
__device__ __forceinline__ uint32_t s2u(const void* p) {
    uint32_t a;
    asm("{ .reg .u64 t; cvta.to.shared.u64 t, %1; cvt.u32.u64 %0, t; }" : "=r"(a) : "l"(p));
    return a;
}
#define CP16(dst, src) \
    asm volatile("cp.async.cg.shared.global [%0], [%1], 16;" :: "r"(dst), "l"(src))
#define CP_COMMIT() asm volatile("cp.async.commit_group;" ::: "memory")
#define CP_WAIT(n)  asm volatile("cp.async.wait_group %0;" :: "n"(n) : "memory")

#define LDSM4(r0, r1, r2, r3, a) \
    asm volatile("ldmatrix.sync.aligned.m8n8.x4.shared.b16 {%0,%1,%2,%3}, [%4];" \
                 : "=r"(r0), "=r"(r1), "=r"(r2), "=r"(r3) : "r"(a))

#define MMA16816(d, a, b) \
    asm volatile("mma.sync.aligned.m16n8k16.row.col.f32.bf16.bf16.f32 " \
                 "{%0,%1,%2,%3}, {%4,%5,%6,%7}, {%8,%9}, {%0,%1,%2,%3};" \
                 : "+f"((d)[0]), "+f"((d)[1]), "+f"((d)[2]), "+f"((d)[3]) \
                 : "r"((a)[0]), "r"((a)[1]), "r"((a)[2]), "r"((a)[3]), \
                   "r"((b)[0]), "r"((b)[1]))

// smem tile: rows of 32 bf16 (64B), 16B chunks XOR-swizzled by (row & 3)
__device__ __forceinline__ uint32_t swz(uint32_t row, uint32_t chunk) {
    return row * 64u + ((chunk ^ (row & 3u)) << 4);
}

#define NSTAGE 4
#define STAGE_BYTES 16384          // A 8KB + B 8KB
#define SMEM_TOTAL (NSTAGE * STAGE_BYTES)

// ===========================================================================
// Split-bf16 NT GEMM: C = alpha*(Ah@Bh^T + Ah@Bl^T + Al@Bh^T) + bias
// Tile 128x128x32, 256 threads, warp tile 64x32. Batched via z.
// ===========================================================================
__global__ __launch_bounds__(256)
void gemm_split(const bf16* __restrict__ Ahi, const bf16* __restrict__ Alo,
                const bf16* __restrict__ Bhi, const bf16* __restrict__ Blo,
                float* __restrict__ Cf, bf16* __restrict__ Chi, bf16* __restrict__ Clo,
                const float* __restrict__ bias,
                int K, int lda, int ldb, int ldc, int zdiv,
                long long zAh, long long zAl, long long zBh, long long zBl,
                long long zCh, long long zCl, float alpha)
{
    extern __shared__ __align__(1024) char smem[];
    const uint32_t sb = s2u(smem);
    const int tid = threadIdx.x;
    const int wid = tid >> 5, lane = tid & 31;
    const int wm = wid & 1, wn = wid >> 1;       // 2 x 4 warp grid

    const int z = blockIdx.z, zh = z / zdiv, zl = z % zdiv;
    const bf16* A0 = Ahi + zh * zAh + zl * zAl;
    const bf16* A1 = Alo + zh * zAh + zl * zAl;
    const bf16* B0 = Bhi + zh * zBh + zl * zBl;
    const bf16* B1 = Blo + zh * zBh + zl * zBl;
    const long long coff = zh * zCh + zl * zCl;
    const int bm = blockIdx.y << 7, bn = blockIdx.x << 7;

    const int nk = K >> 5;          // k-chunks of 32
    const int T  = 3 * nk;          // hi*hi, hi*lo, lo*hi

    const int lrow = tid >> 1;
    const int lkc  = (tid & 1) * 2;

    auto issue_loads = [&](int c, int s) {
        const int p  = c / nk;
        const int kk = c - p * nk;
        const bf16* Ab = (p == 2) ? A1 : A0;
        const bf16* Bb = (p == 1) ? B1 : B0;
        const bf16* ag = Ab + (long long)(bm + lrow) * lda + kk * 32 + lkc * 8;
        const bf16* bg = Bb + (long long)(bn + lrow) * ldb + kk * 32 + lkc * 8;
        const uint32_t abase = sb + s * STAGE_BYTES;
        const uint32_t bbase = abase + 8192;
        CP16(abase + swz(lrow, lkc),     ag);
        CP16(abase + swz(lrow, lkc + 1), ag + 8);
        CP16(bbase + swz(lrow, lkc),     bg);
        CP16(bbase + swz(lrow, lkc + 1), bg + 8);
    };

    float acc[4][4][4];
#pragma unroll
    for (int i = 0; i < 4; ++i)
#pragma unroll
        for (int j = 0; j < 4; ++j)
#pragma unroll
            for (int r = 0; r < 4; ++r) acc[i][j][r] = 0.0f;

#pragma unroll
    for (int s = 0; s < NSTAGE - 1; ++s) { issue_loads(s, s); CP_COMMIT(); }

    const int l15 = lane & 15;
    const int lhi = lane >> 4;

    for (int i = 0; i < T; ++i) {
        const int st = i & (NSTAGE - 1);
        CP_WAIT(NSTAGE - 2);
        __syncthreads();

        if (i + NSTAGE - 1 < T) issue_loads(i + NSTAGE - 1, (i + NSTAGE - 1) & (NSTAGE - 1));
        CP_COMMIT();

        const uint32_t abase = sb + st * STAGE_BYTES;
        const uint32_t bbase = abase + 8192;

#pragma unroll
        for (int kk = 0; kk < 2; ++kk) {
            uint32_t af[4][4], bfr[4][2];
#pragma unroll
            for (int mi = 0; mi < 4; ++mi) {
                const uint32_t row = wm * 64 + mi * 16 + l15;
                LDSM4(af[mi][0], af[mi][1], af[mi][2], af[mi][3],
                      abase + swz(row, kk * 2 + lhi));
            }
#pragma unroll
            for (int jj = 0; jj < 2; ++jj) {
                uint32_t r0, r1, r2, r3;
                const uint32_t row = wn * 32 + jj * 16 + l15;
                LDSM4(r0, r1, r2, r3, bbase + swz(row, kk * 2 + lhi));
                bfr[jj * 2][0] = r0;     bfr[jj * 2][1] = r2;
                bfr[jj * 2 + 1][0] = r1; bfr[jj * 2 + 1][1] = r3;
            }
#pragma unroll
            for (int mi = 0; mi < 4; ++mi)
#pragma unroll
                for (int j = 0; j < 4; ++j)
                    MMA16816(acc[mi][j], af[mi], bfr[j]);
        }
    }

    // ---------------- epilogue ----------------
    const int r0 = lane >> 2, c0 = (lane & 3) * 2;
#pragma unroll
    for (int mi = 0; mi < 4; ++mi) {
#pragma unroll
        for (int rr = 0; rr < 2; ++rr) {
            const int m = bm + wm * 64 + mi * 16 + r0 + rr * 8;
            const long long rbase = coff + (long long)m * ldc;
#pragma unroll
            for (int j = 0; j < 4; ++j) {
                const int n = bn + wn * 32 + j * 8 + c0;
                float x0 = alpha * acc[mi][j][rr * 2 + 0];
                float x1 = alpha * acc[mi][j][rr * 2 + 1];
                if (bias) { x0 += __ldg(&bias[n]); x1 += __ldg(&bias[n + 1]); }
                if (Cf) *(float2*)(Cf + rbase + n) = make_float2(x0, x1);
                if (Chi) {
                    bf16 h0 = __float2bfloat16(x0), h1 = __float2bfloat16(x1);
                    bf16 l0 = __float2bfloat16(x0 - __bfloat162float(h0));
                    bf16 l1 = __float2bfloat16(x1 - __bfloat162float(h1));
                    bf16 hp[2] = {h0, h1}, lp[2] = {l0, l1};
                    *(uint32_t*)(Chi + rbase + n) = *(uint32_t*)hp;
                    *(uint32_t*)(Clo + rbase + n) = *(uint32_t*)lp;
                }
            }
        }
    }
}

// ===========================================================================
// elementwise helpers
// ===========================================================================
__global__ __launch_bounds__(256)
void split_fp32(const float* __restrict__ x, bf16* __restrict__ hi, bf16* __restrict__ lo)
{
    long long i = ((long long)blockIdx.x * 256 + threadIdx.x) * 4;
    float4 v = *(const float4*)(x + i);
    bf16 h[4], l[4];
    float a[4] = {v.x, v.y, v.z, v.w};
#pragma unroll
    for (int j = 0; j < 4; ++j) {
        h[j] = __float2bfloat16(a[j]);
        l[j] = __float2bfloat16(a[j] - __bfloat162float(h[j]));
    }
    *(uint2*)(hi + i) = *(uint2*)h;
    *(uint2*)(lo + i) = *(uint2*)l;
}

__global__ void concat_bias(const float* __restrict__ bq, const float* __restrict__ bk,
                            const float* __restrict__ bv, float* __restrict__ bc)
{
    int i = blockIdx.x * 256 + threadIdx.x;
    if (i < 4352) {
        float v;
        if (i < 4096)      v = bq[i];
        else if (i < 4224) v = bk[i - 4096];
        else               v = bv[i - 4224];
        bc[i] = v;
    }
}

// V slice of QKV (col 4224, ld 4352) -> VT (B, D, S) hi/lo
__global__ __launch_bounds__(256)
void transpose_v_split(const bf16* __restrict__ qkvh, const bf16* __restrict__ qkvl,
                       bf16* __restrict__ th, bf16* __restrict__ tl)
{
    long long i = (long long)blockIdx.x * 256 + threadIdx.x;
    int d = (int)(i & 127);
    int t = (int)((i >> 7) & 2047);
    int b = (int)(i >> 18);
    long long src = (long long)(b * 2048 + t) * 4352 + 4224 + d;
    long long o   = ((long long)b * 128 + d) * 2048 + t;
    th[o] = qkvh[src];
    tl[o] = qkvl[src];
}

__global__ __launch_bounds__(256)
void softmax_split(const float* __restrict__ S, bf16* __restrict__ Ph, bf16* __restrict__ Pl)
{
    const float* row = S + (long long)blockIdx.x * 2048;
    const int tid = threadIdx.x;
    float4 v0 = ((const float4*)row)[tid * 2];
    float4 v1 = ((const float4*)row)[tid * 2 + 1];

    float m = fmaxf(fmaxf(fmaxf(v0.x, v0.y), fmaxf(v0.z, v0.w)),
                    fmaxf(fmaxf(v1.x, v1.y), fmaxf(v1.z, v1.w)));
#pragma unroll
    for (int o = 16; o > 0; o >>= 1) m = fmaxf(m, __shfl_xor_sync(~0u, m, o));
    __shared__ float redm[8], reds[8];
    if ((tid & 31) == 0) redm[tid >> 5] = m;
    __syncthreads();
    float mm = redm[0];
#pragma unroll
    for (int i = 1; i < 8; ++i) mm = fmaxf(mm, redm[i]);

    float e[8] = {__expf(v0.x - mm), __expf(v0.y - mm), __expf(v0.z - mm), __expf(v0.w - mm),
                  __expf(v1.x - mm), __expf(v1.y - mm), __expf(v1.z - mm), __expf(v1.w - mm)};
    float s = e[0] + e[1] + e[2] + e[3] + e[4] + e[5] + e[6] + e[7];
#pragma unroll
    for (int o = 16; o > 0; o >>= 1) s += __shfl_xor_sync(~0u, s, o);
    if ((tid & 31) == 0) reds[tid >> 5] = s;
    __syncthreads();
    float tot = 0.0f;
#pragma unroll
    for (int i = 0; i < 8; ++i) tot += reds[i];
    const float inv = 1.0f / tot;

    bf16 h8[8], l8[8];
#pragma unroll
    for (int j = 0; j < 8; ++j) {
        float p = e[j] * inv;
        bf16 hh = __float2bfloat16(p);
        h8[j] = hh;
        l8[j] = __float2bfloat16(p - __bfloat162float(hh));
    }
    long long base = (long long)blockIdx.x * 2048 + tid * 8;
    *(uint4*)(Ph + base) = *(uint4*)h8;
    *(uint4*)(Pl + base) = *(uint4*)l8;
}

__global__ __launch_bounds__(256)
void permute_o_split(const float* __restrict__ O, bf16* __restrict__ Xh, bf16* __restrict__ Xl)
{
    long long i = (long long)blockIdx.x * 256 + threadIdx.x;
    int dd = (int)(i & 127);
    int ss = (int)((i >> 7) & 2047);
    int h  = (int)((i >> 18) & 31);
    int b  = (int)(i >> 23);
    int r  = h * 64 + (dd >> 1);
    int c  = (dd & 1) * 2048 + ss;
    long long o = ((long long)(b * 2048 + r)) * 4096 + c;
    float x = O[i];
    bf16 hh = __float2bfloat16(x);
    Xh[o] = hh;
    Xl[o] = __float2bfloat16(x - __bfloat162float(hh));
}

// ===========================================================================
extern "C" void kernel_launch(void* const* d_in, const int* in_sizes, int n_in,
                              void* d_out, int out_size)
{
    const float* hs = (const float*)d_in[0];
    const float* Wq = (const float*)d_in[1];
    const float* bq = (const float*)d_in[2];
    const float* Wk = (const float*)d_in[3];
    const float* bk = (const float*)d_in[4];
    const float* Wv = (const float*)d_in[5];
    const float* bv = (const float*)d_in[6];
    const float* Wo = (const float*)d_in[7];
    const float* bo = (const float*)d_in[8];
    float* out = (float*)d_out;

    bf16 *hsh, *hsl, *wch, *wcl, *woh, *wol;
    bf16 *qkvh, *qkvl, *vth, *vtl, *ph, *pl, *xh, *xl;
    float *pS, *pO, *bc;
    cudaGetSymbolAddress((void**)&hsh, g_hs_hi);  cudaGetSymbolAddress((void**)&hsl, g_hs_lo);
    cudaGetSymbolAddress((void**)&wch, g_Wc_hi);  cudaGetSymbolAddress((void**)&wcl, g_Wc_lo);
    cudaGetSymbolAddress((void**)&woh, g_Wo_hi);  cudaGetSymbolAddress((void**)&wol, g_Wo_lo);
    cudaGetSymbolAddress((void**)&qkvh, g_QKV_hi); cudaGetSymbolAddress((void**)&qkvl, g_QKV_lo);
    cudaGetSymbolAddress((void**)&vth, g_VT_hi);  cudaGetSymbolAddress((void**)&vtl, g_VT_lo);
    cudaGetSymbolAddress((void**)&ph,  g_P_hi);   cudaGetSymbolAddress((void**)&pl,  g_P_lo);
    cudaGetSymbolAddress((void**)&xh,  g_X_hi);   cudaGetSymbolAddress((void**)&xl,  g_X_lo);
    cudaGetSymbolAddress((void**)&pS,  g_S);      cudaGetSymbolAddress((void**)&pO,  g_O);
    cudaGetSymbolAddress((void**)&bc,  g_bc);

    cudaFuncSetAttribute(gemm_split, cudaFuncAttributeMaxDynamicSharedMemorySize, SMEM_TOTAL);

    const float scale = 0.08838834764831845f;  // 1/sqrt(128)

    // splits: hs, combined weight [Wq; Wk; Wv], Wo
    split_fp32<<<16384, 256>>>(hs, hsh, hsl);
    split_fp32<<<16384, 256>>>(Wq, wch, wcl);
    split_fp32<<<512,   256>>>(Wk, wch + 16777216, wcl + 16777216);
    split_fp32<<<512,   256>>>(Wv, wch + 16777216 + 524288, wcl + 16777216 + 524288);
    split_fp32<<<16384, 256>>>(Wo, woh, wol);
    concat_bias<<<17, 256>>>(bq, bk, bv, bc);

    // QKV = hs @ Wc^T + bc -> split   (4096 x 4352 x 4096), one launch
    gemm_split<<<dim3(34, 32, 1), 256, SMEM_TOTAL>>>(
        hsh, hsl, wch, wcl, nullptr, qkvh, qkvl, bc,
        4096, 4096, 4096, 4352, 1, 0, 0, 0, 0, 0, 0, 1.0f);

    // VT (B,D,S) from the V columns of QKV
    transpose_v_split<<<2048, 256>>>(qkvh, qkvl, vth, vtl);

    // S[z=b*32+h] = scale * Q_slice @ K_b^T   (2048 x 2048 x 128, 64 batches)
    // A = QKV cols [h*128, h*128+128), B = QKV cols [4096, 4224) of batch b
    gemm_split<<<dim3(16, 16, 64), 256, SMEM_TOTAL>>>(
        qkvh, qkvl, qkvh + 4096, qkvl + 4096, pS, nullptr, nullptr, nullptr,
        128, 4352, 4352, 2048, 32,
        2048LL * 4352, 128LL, 2048LL * 4352, 0LL,
        32LL * 2048 * 2048, 2048LL * 2048, scale);

    softmax_split<<<64 * 2048, 256>>>(pS, ph, pl);

    // O[z] = P[z] @ VT_b^T            (2048 x 128 x 2048, 64 batches)
    gemm_split<<<dim3(1, 16, 64), 256, SMEM_TOTAL>>>(
        ph, pl, vth, vtl, pO, nullptr, nullptr, nullptr,
        2048, 2048, 2048, 128, 32,
        32LL * 2048 * 2048, 2048LL * 2048, 128LL * 2048, 0LL,
        32LL * 2048 * 128, 2048LL * 128, 1.0f);

    permute_o_split<<<65536, 256>>>(pO, xh, xl);

    // out = X @ Wo^T + bo             (4096 x 4096 x 4096)
    gemm_split<<<dim3(32, 32, 1), 256, SMEM_TOTAL>>>(
        xh, xl, woh, wol, out, nullptr, nullptr, bo,
        4096, 4096, 4096, 4096, 1, 0, 0, 0, 0, 0, 0, 1.0f);
}

// round 6
// speedup vs baseline: 2.0231x; 1.1167x over previous
#include <cuda_runtime.h>
#include <cuda_bf16.h>
#include <cstdint>

typedef __nv_bfloat16 bf16;

// ===========================================================================
// MQA block: B=2, S=2048, H=4096, NH=32, D=128.
// Round 5: fused flash attention (S GEMM + softmax + PV in one kernel),
// split-bf16 HMMA (hi/lo, 3 passes) everywhere, fp32 accum.
// ===========================================================================

// ---------------- scratch ----------------
__device__ __align__(16) bf16 g_hs_hi[16777216], g_hs_lo[16777216];
__device__ __align__(16) bf16 g_Wc_hi[17825792], g_Wc_lo[17825792];   // [4352][4096]
__device__ __align__(16) float g_bc[4352];
__device__ __align__(16) bf16 g_Wo_hi[16777216], g_Wo_lo[16777216];
__device__ __align__(16) bf16 g_QKV_hi[17825792], g_QKV_lo[17825792]; // [4096][4352]
__device__ __align__(16) bf16 g_VT_hi[524288],  g_VT_lo[524288];      // (B,D,S)
__device__ __align__(16) float g_O[16777216];                         // (64,2048,128)
__device__ __align__(16) bf16 g_X_hi[16777216],  g_X_lo[16777216];

// ---------------- PTX helpers ----------------
__device__ __forceinline__ uint32_t s2u(const void* p) {
    uint32_t a;
    asm("{ .reg .u64 t; cvta.to.shared.u64 t, %1; cvt.u32.u64 %0, t; }" : "=r"(a) : "l"(p));
    return a;
}
#define CP16(dst, src) \
    asm volatile("cp.async.cg.shared.global [%0], [%1], 16;" :: "r"(dst), "l"(src))
#define CP_COMMIT() asm volatile("cp.async.commit_group;" ::: "memory")
#define CP_WAIT(n)  asm volatile("cp.async.wait_group %0;" :: "n"(n) : "memory")

#define LDSM4(r0, r1, r2, r3, a) \
    asm volatile("ldmatrix.sync.aligned.m8n8.x4.shared.b16 {%0,%1,%2,%3}, [%4];" \
                 : "=r"(r0), "=r"(r1), "=r"(r2), "=r"(r3) : "r"(a))

#define MMA16816(d, a, b) \
    asm volatile("mma.sync.aligned.m16n8k16.row.col.f32.bf16.bf16.f32 " \
                 "{%0,%1,%2,%3}, {%4,%5,%6,%7}, {%8,%9}, {%0,%1,%2,%3};" \
                 : "+f"((d)[0]), "+f"((d)[1]), "+f"((d)[2]), "+f"((d)[3]) \
                 : "r"((a)[0]), "r"((a)[1]), "r"((a)[2]), "r"((a)[3]), \
                   "r"((b)[0]), "r"((b)[1]))

// 64B-row swizzle (GEMM tiles: rows of 32 bf16)
__device__ __forceinline__ uint32_t swz(uint32_t row, uint32_t chunk) {
    return row * 64u + ((chunk ^ (row & 3u)) << 4);
}
// 256B-row swizzle (flash tiles: rows of 128 bf16, 16 chunks of 16B)
__device__ __forceinline__ uint32_t swz256(uint32_t row, uint32_t chunk) {
    return row * 256u + ((chunk ^ (row & 7u)) << 4);
}

__device__ __forceinline__ uint32_t pack_bf2(bf16 lo, bf16 hi) {
    return (uint32_t)__bfloat16_as_ushort(hi) << 16 | __bfloat16_as_ushort(lo);
}

#define NSTAGE 4
#define STAGE_BYTES 16384
#define SMEM_TOTAL (NSTAGE * STAGE_BYTES)

// ===========================================================================
// Split-bf16 NT GEMM (unchanged): C = alpha*(Ah@Bh^T+Ah@Bl^T+Al@Bh^T)+bias
// ===========================================================================
__global__ __launch_bounds__(256)
void gemm_split(const bf16* __restrict__ Ahi, const bf16* __restrict__ Alo,
                const bf16* __restrict__ Bhi, const bf16* __restrict__ Blo,
                float* __restrict__ Cf, bf16* __restrict__ Chi, bf16* __restrict__ Clo,
                const float* __restrict__ bias,
                int K, int lda, int ldb, int ldc, float alpha)
{
    extern __shared__ __align__(1024) char smem[];
    const uint32_t sb = s2u(smem);
    const int tid = threadIdx.x;
    const int wid = tid >> 5, lane = tid & 31;
    const int wm = wid & 1, wn = wid >> 1;

    const int bm = blockIdx.y << 7, bn = blockIdx.x << 7;
    const int nk = K >> 5;
    const int T  = 3 * nk;

    const int lrow = tid >> 1;
    const int lkc  = (tid & 1) * 2;

    auto issue_loads = [&](int c, int s) {
        const int p  = c / nk;
        const int kk = c - p * nk;
        const bf16* Ab = (p == 2) ? Alo : Ahi;
        const bf16* Bb = (p == 1) ? Blo : Bhi;
        const bf16* ag = Ab + (long long)(bm + lrow) * lda + kk * 32 + lkc * 8;
        const bf16* bg = Bb + (long long)(bn + lrow) * ldb + kk * 32 + lkc * 8;
        const uint32_t abase = sb + s * STAGE_BYTES;
        const uint32_t bbase = abase + 8192;
        CP16(abase + swz(lrow, lkc),     ag);
        CP16(abase + swz(lrow, lkc + 1), ag + 8);
        CP16(bbase + swz(lrow, lkc),     bg);
        CP16(bbase + swz(lrow, lkc + 1), bg + 8);
    };

    float acc[4][4][4];
#pragma unroll
    for (int i = 0; i < 4; ++i)
#pragma unroll
        for (int j = 0; j < 4; ++j)
#pragma unroll
            for (int r = 0; r < 4; ++r) acc[i][j][r] = 0.0f;

#pragma unroll
    for (int s = 0; s < NSTAGE - 1; ++s) { issue_loads(s, s); CP_COMMIT(); }

    const int l15 = lane & 15;
    const int lhi = lane >> 4;

    for (int i = 0; i < T; ++i) {
        const int st = i & (NSTAGE - 1);
        CP_WAIT(NSTAGE - 2);
        __syncthreads();

        if (i + NSTAGE - 1 < T) issue_loads(i + NSTAGE - 1, (i + NSTAGE - 1) & (NSTAGE - 1));
        CP_COMMIT();

        const uint32_t abase = sb + st * STAGE_BYTES;
        const uint32_t bbase = abase + 8192;

#pragma unroll
        for (int kk = 0; kk < 2; ++kk) {
            uint32_t af[4][4], bfr[4][2];
#pragma unroll
            for (int mi = 0; mi < 4; ++mi) {
                const uint32_t row = wm * 64 + mi * 16 + l15;
                LDSM4(af[mi][0], af[mi][1], af[mi][2], af[mi][3],
                      abase + swz(row, kk * 2 + lhi));
            }
#pragma unroll
            for (int jj = 0; jj < 2; ++jj) {
                uint32_t r0, r1, r2, r3;
                const uint32_t row = wn * 32 + jj * 16 + l15;
                LDSM4(r0, r1, r2, r3, bbase + swz(row, kk * 2 + lhi));
                bfr[jj * 2][0] = r0;     bfr[jj * 2][1] = r2;
                bfr[jj * 2 + 1][0] = r1; bfr[jj * 2 + 1][1] = r3;
            }
#pragma unroll
            for (int mi = 0; mi < 4; ++mi)
#pragma unroll
                for (int j = 0; j < 4; ++j)
                    MMA16816(acc[mi][j], af[mi], bfr[j]);
        }
    }

    const int r0 = lane >> 2, c0 = (lane & 3) * 2;
#pragma unroll
    for (int mi = 0; mi < 4; ++mi) {
#pragma unroll
        for (int rr = 0; rr < 2; ++rr) {
            const int m = bm + wm * 64 + mi * 16 + r0 + rr * 8;
            const long long rbase = (long long)m * ldc;
#pragma unroll
            for (int j = 0; j < 4; ++j) {
                const int n = bn + wn * 32 + j * 8 + c0;
                float x0 = alpha * acc[mi][j][rr * 2 + 0];
                float x1 = alpha * acc[mi][j][rr * 2 + 1];
                if (bias) { x0 += __ldg(&bias[n]); x1 += __ldg(&bias[n + 1]); }
                if (Cf) *(float2*)(Cf + rbase + n) = make_float2(x0, x1);
                if (Chi) {
                    bf16 h0 = __float2bfloat16(x0), h1 = __float2bfloat16(x1);
                    bf16 l0 = __float2bfloat16(x0 - __bfloat162float(h0));
                    bf16 l1 = __float2bfloat16(x1 - __bfloat162float(h1));
                    *(uint32_t*)(Chi + rbase + n) = pack_bf2(h0, h1);
                    *(uint32_t*)(Clo + rbase + n) = pack_bf2(l0, l1);
                }
            }
        }
    }
}

// ===========================================================================
// Fused flash attention. grid (16 q-tiles, 64 z=b*32+h), 256 thr, 8 warps.
// smem: Qh Ql Kh Kl Vh Vl, each 128x128 bf16 (32KB) = 192KB. 1 CTA/SM.
// Warp w owns q-rows [w*16, w*16+16).
// ===========================================================================
#define FLASH_SMEM 196608
__global__ __launch_bounds__(256, 1)
void flash_attn(const bf16* __restrict__ qkvh, const bf16* __restrict__ qkvl,
                const bf16* __restrict__ vth, const bf16* __restrict__ vtl,
                float* __restrict__ O)
{
    extern __shared__ __align__(1024) char smem[];
    const uint32_t sb = s2u(smem);
    const uint32_t QH = sb, QL = sb + 32768, KH = sb + 65536, KL = sb + 98304,
                   VH = sb + 131072, VL = sb + 163840;
    const int tid = threadIdx.x, wid = tid >> 5, lane = tid & 31;
    const int z = blockIdx.y, b = z >> 5, h = z & 31;
    const int qt = blockIdx.x;
    const int l15 = lane & 15, lhi = lane >> 4;
    const float scale = 0.08838834764831845f;

    const int lrow = tid >> 1;           // tile row 0..127
    const int lcb  = (tid & 1) * 8;      // chunk base 0 or 8

    const bf16* Qh_src = qkvh + (long long)(b * 2048 + qt * 128 + lrow) * 4352 + h * 128;
    const bf16* Ql_src = qkvl + (long long)(b * 2048 + qt * 128 + lrow) * 4352 + h * 128;
    const bf16* Kh_src = qkvh + (long long)(b * 2048 + lrow) * 4352 + 4096;
    const bf16* Kl_src = qkvl + (long long)(b * 2048 + lrow) * 4352 + 4096;
    const bf16* Vh_src = vth + (long long)(b * 128 + lrow) * 2048;
    const bf16* Vl_src = vtl + (long long)(b * 128 + lrow) * 2048;

    auto ld_tile = [&](uint32_t dh, uint32_t dl, const bf16* sh, const bf16* sl) {
#pragma unroll
        for (int c = 0; c < 8; ++c) {
            const uint32_t off = swz256(lrow, lcb + c);
            CP16(dh + off, sh + (lcb + c) * 8);
            CP16(dl + off, sl + (lcb + c) * 8);
        }
    };

    // prologue: Q, K_0
    ld_tile(QH, QL, Qh_src, Ql_src); CP_COMMIT();
    ld_tile(KH, KL, Kh_src, Kl_src); CP_COMMIT();

    float acc_o[16][4];
#pragma unroll
    for (int a = 0; a < 16; ++a)
#pragma unroll
        for (int i = 0; i < 4; ++i) acc_o[a][i] = 0.0f;
    float m0 = -1e30f, m1 = -1e30f, l0 = 0.0f, l1 = 0.0f;

    for (int j = 0; j < 16; ++j) {
        __syncthreads();                         // V buffer free (prev PV done)
        ld_tile(VH, VL, Vh_src + j * 128, Vl_src + j * 128); CP_COMMIT();
        CP_WAIT(1);                              // K_j (and Q) resident
        __syncthreads();

        // ---- S = Qh@Kh^T + Qh@Kl^T + Ql@Kh^T (fp32 acc) ----
        float acc_s[16][4];
#pragma unroll
        for (int a = 0; a < 16; ++a)
#pragma unroll
            for (int i = 0; i < 4; ++i) acc_s[a][i] = 0.0f;

#pragma unroll
        for (int kk = 0; kk < 8; ++kk) {
            uint32_t ah[4], al[4];
            LDSM4(ah[0], ah[1], ah[2], ah[3], QH + swz256(wid * 16 + l15, kk * 2 + lhi));
            LDSM4(al[0], al[1], al[2], al[3], QL + swz256(wid * 16 + l15, kk * 2 + lhi));
#pragma unroll
            for (int ng = 0; ng < 8; ++ng) {
                uint32_t r0, r1, r2, r3;
                LDSM4(r0, r1, r2, r3, KH + swz256(ng * 16 + l15, kk * 2 + lhi));
                uint32_t bh0[2] = {r0, r2}, bh1[2] = {r1, r3};
                MMA16816(acc_s[ng * 2],     ah, bh0);
                MMA16816(acc_s[ng * 2 + 1], ah, bh1);
                MMA16816(acc_s[ng * 2],     al, bh0);
                MMA16816(acc_s[ng * 2 + 1], al, bh1);
                LDSM4(r0, r1, r2, r3, KL + swz256(ng * 16 + l15, kk * 2 + lhi));
                uint32_t bl0[2] = {r0, r2}, bl1[2] = {r1, r3};
                MMA16816(acc_s[ng * 2],     ah, bl0);
                MMA16816(acc_s[ng * 2 + 1], ah, bl1);
            }
        }

        __syncthreads();                         // K_j reads done
        if (j < 15) {                            // prefetch K_{j+1} during softmax+PV
            ld_tile(KH, KL, Kh_src + (long long)(j + 1) * 128 * 4352,
                            Kl_src + (long long)(j + 1) * 128 * 4352);
            CP_COMMIT();
        }

        // ---- online softmax ----
        float rm0 = -1e30f, rm1 = -1e30f;
#pragma unroll
        for (int a = 0; a < 16; ++a) {
            acc_s[a][0] *= scale; acc_s[a][1] *= scale;
            acc_s[a][2] *= scale; acc_s[a][3] *= scale;
            rm0 = fmaxf(rm0, fmaxf(acc_s[a][0], acc_s[a][1]));
            rm1 = fmaxf(rm1, fmaxf(acc_s[a][2], acc_s[a][3]));
        }
        rm0 = fmaxf(rm0, __shfl_xor_sync(~0u, rm0, 1));
        rm0 = fmaxf(rm0, __shfl_xor_sync(~0u, rm0, 2));
        rm1 = fmaxf(rm1, __shfl_xor_sync(~0u, rm1, 1));
        rm1 = fmaxf(rm1, __shfl_xor_sync(~0u, rm1, 2));
        const float mn0 = fmaxf(m0, rm0), mn1 = fmaxf(m1, rm1);
        const float f0 = __expf(m0 - mn0), f1 = __expf(m1 - mn1);
        l0 *= f0; l1 *= f1;
        m0 = mn0; m1 = mn1;
#pragma unroll
        for (int a = 0; a < 16; ++a) {
            acc_o[a][0] *= f0; acc_o[a][1] *= f0;
            acc_o[a][2] *= f1; acc_o[a][3] *= f1;
        }

        // P = exp(S - m) -> split bf16, packed as m16k16 A-fragments
        uint32_t p_h[32], p_l[32];
#pragma unroll
        for (int a = 0; a < 16; ++a) {
            float p00 = __expf(acc_s[a][0] - mn0), p01 = __expf(acc_s[a][1] - mn0);
            float p10 = __expf(acc_s[a][2] - mn1), p11 = __expf(acc_s[a][3] - mn1);
            l0 += p00 + p01; l1 += p10 + p11;
            bf16 h00 = __float2bfloat16(p00), h01 = __float2bfloat16(p01);
            bf16 h10 = __float2bfloat16(p10), h11 = __float2bfloat16(p11);
            bf16 e00 = __float2bfloat16(p00 - __bfloat162float(h00));
            bf16 e01 = __float2bfloat16(p01 - __bfloat162float(h01));
            bf16 e10 = __float2bfloat16(p10 - __bfloat162float(h10));
            bf16 e11 = __float2bfloat16(p11 - __bfloat162float(h11));
            p_h[a * 2]     = pack_bf2(h00, h01);
            p_h[a * 2 + 1] = pack_bf2(h10, h11);
            p_l[a * 2]     = pack_bf2(e00, e01);
            p_l[a * 2 + 1] = pack_bf2(e10, e11);
        }

        CP_WAIT(1);                              // V_j resident (K_{j+1} may fly)
        __syncthreads();

        // ---- O += Ph@Vh + Ph@Vl + Pl@Vh ----
#pragma unroll
        for (int kk = 0; kk < 8; ++kk) {
            uint32_t afh[4] = {p_h[kk * 4], p_h[kk * 4 + 1], p_h[kk * 4 + 2], p_h[kk * 4 + 3]};
            uint32_t afl[4] = {p_l[kk * 4], p_l[kk * 4 + 1], p_l[kk * 4 + 2], p_l[kk * 4 + 3]};
#pragma unroll
            for (int ng = 0; ng < 8; ++ng) {
                uint32_t r0, r1, r2, r3;
                LDSM4(r0, r1, r2, r3, VH + swz256(ng * 16 + l15, kk * 2 + lhi));
                uint32_t bh0[2] = {r0, r2}, bh1[2] = {r1, r3};
                MMA16816(acc_o[ng * 2],     afh, bh0);
                MMA16816(acc_o[ng * 2 + 1], afh, bh1);
                MMA16816(acc_o[ng * 2],     afl, bh0);
                MMA16816(acc_o[ng * 2 + 1], afl, bh1);
                LDSM4(r0, r1, r2, r3, VL + swz256(ng * 16 + l15, kk * 2 + lhi));
                uint32_t bl0[2] = {r0, r2}, bl1[2] = {r1, r3};
                MMA16816(acc_o[ng * 2],     afh, bl0);
                MMA16816(acc_o[ng * 2 + 1], afh, bl1);
            }
        }
    }

    // ---- epilogue: normalize and write O ----
    l0 += __shfl_xor_sync(~0u, l0, 1); l0 += __shfl_xor_sync(~0u, l0, 2);
    l1 += __shfl_xor_sync(~0u, l1, 1); l1 += __shfl_xor_sync(~0u, l1, 2);
    const float inv0 = 1.0f / l0, inv1 = 1.0f / l1;
    const int r = lane >> 2, c2 = (lane & 3) * 2;
    const long long base = (long long)z * 2048 * 128 + (long long)(qt * 128 + wid * 16) * 128;
#pragma unroll
    for (int ng = 0; ng < 16; ++ng) {
        const int col = ng * 8 + c2;
        *(float2*)(O + base + (long long)r * 128 + col) =
            make_float2(acc_o[ng][0] * inv0, acc_o[ng][1] * inv0);
        *(float2*)(O + base + (long long)(r + 8) * 128 + col) =
            make_float2(acc_o[ng][2] * inv1, acc_o[ng][3] * inv1);
    }
}

// ===========================================================================
// elementwise helpers
// ===========================================================================
__global__ __launch_bounds__(256)
void split_fp32(const float* __restrict__ x, bf16* __restrict__ hi, bf16* __restrict__ lo)
{
    long long i = ((long long)blockIdx.x * 256 + threadIdx.x) * 4;
    float4 v = *(const float4*)(x + i);
    bf16 h[4], l[4];
    float a[4] = {v.x, v.y, v.z, v.w};
#pragma unroll
    for (int j = 0; j < 4; ++j) {
        h[j] = __float2bfloat16(a[j]);
        l[j] = __float2bfloat16(a[j] - __bfloat162float(h[j]));
    }
    *(uint2*)(hi + i) = *(uint2*)h;
    *(uint2*)(lo + i) = *(uint2*)l;
}

__global__ void concat_bias(const float* __restrict__ bq, const float* __restrict__ bk,
                            const float* __restrict__ bv, float* __restrict__ bc)
{
    int i = blockIdx.x * 256 + threadIdx.x;
    if (i < 4352) {
        float v;
        if (i < 4096)      v = bq[i];
        else if (i < 4224) v = bk[i - 4096];
        else               v = bv[i - 4224];
        bc[i] = v;
    }
}

__global__ __launch_bounds__(256)
void transpose_v_split(const bf16* __restrict__ qkvh, const bf16* __restrict__ qkvl,
                       bf16* __restrict__ th, bf16* __restrict__ tl)
{
    long long i = (long long)blockIdx.x * 256 + threadIdx.x;
    int d = (int)(i & 127);
    int t = (int)((i >> 7) & 2047);
    int b = (int)(i >> 18);
    long long src = (long long)(b * 2048 + t) * 4352 + 4224 + d;
    long long o   = ((long long)b * 128 + d) * 2048 + t;
    th[o] = qkvh[src];
    tl[o] = qkvl[src];
}

__global__ __launch_bounds__(256)
void permute_o_split(const float* __restrict__ O, bf16* __restrict__ Xh, bf16* __restrict__ Xl)
{
    long long i = (long long)blockIdx.x * 256 + threadIdx.x;
    int dd = (int)(i & 127);
    int ss = (int)((i >> 7) & 2047);
    int h  = (int)((i >> 18) & 31);
    int b  = (int)(i >> 23);
    int r  = h * 64 + (dd >> 1);
    int c  = (dd & 1) * 2048 + ss;
    long long o = ((long long)(b * 2048 + r)) * 4096 + c;
    float x = O[i];
    bf16 hh = __float2bfloat16(x);
    Xh[o] = hh;
    Xl[o] = __float2bfloat16(x - __bfloat162float(hh));
}

// ===========================================================================
extern "C" void kernel_launch(void* const* d_in, const int* in_sizes, int n_in,
                              void* d_out, int out_size)
{
    const float* hs = (const float*)d_in[0];
    const float* Wq = (const float*)d_in[1];
    const float* bq = (const float*)d_in[2];
    const float* Wk = (const float*)d_in[3];
    const float* bk = (const float*)d_in[4];
    const float* Wv = (const float*)d_in[5];
    const float* bv = (const float*)d_in[6];
    const float* Wo = (const float*)d_in[7];
    const float* bo = (const float*)d_in[8];
    float* out = (float*)d_out;

    bf16 *hsh, *hsl, *wch, *wcl, *woh, *wol;
    bf16 *qkvh, *qkvl, *vth, *vtl, *xh, *xl;
    float *pO, *bc;
    cudaGetSymbolAddress((void**)&hsh, g_hs_hi);  cudaGetSymbolAddress((void**)&hsl, g_hs_lo);
    cudaGetSymbolAddress((void**)&wch, g_Wc_hi);  cudaGetSymbolAddress((void**)&wcl, g_Wc_lo);
    cudaGetSymbolAddress((void**)&woh, g_Wo_hi);  cudaGetSymbolAddress((void**)&wol, g_Wo_lo);
    cudaGetSymbolAddress((void**)&qkvh, g_QKV_hi); cudaGetSymbolAddress((void**)&qkvl, g_QKV_lo);
    cudaGetSymbolAddress((void**)&vth, g_VT_hi);  cudaGetSymbolAddress((void**)&vtl, g_VT_lo);
    cudaGetSymbolAddress((void**)&xh,  g_X_hi);   cudaGetSymbolAddress((void**)&xl,  g_X_lo);
    cudaGetSymbolAddress((void**)&pO,  g_O);
    cudaGetSymbolAddress((void**)&bc,  g_bc);

    cudaFuncSetAttribute(gemm_split, cudaFuncAttributeMaxDynamicSharedMemorySize, SMEM_TOTAL);
    cudaFuncSetAttribute(flash_attn, cudaFuncAttributeMaxDynamicSharedMemorySize, FLASH_SMEM);

    // splits: hs, combined weight [Wq; Wk; Wv], Wo
    split_fp32<<<16384, 256>>>(hs, hsh, hsl);
    split_fp32<<<16384, 256>>>(Wq, wch, wcl);
    split_fp32<<<512,   256>>>(Wk, wch + 16777216, wcl + 16777216);
    split_fp32<<<512,   256>>>(Wv, wch + 16777216 + 524288, wcl + 16777216 + 524288);
    split_fp32<<<16384, 256>>>(Wo, woh, wol);
    concat_bias<<<17, 256>>>(bq, bk, bv, bc);

    // QKV = hs @ Wc^T + bc -> split   (4096 x 4352 x 4096)
    gemm_split<<<dim3(34, 32, 1), 256, SMEM_TOTAL>>>(
        hsh, hsl, wch, wcl, nullptr, qkvh, qkvl, bc,
        4096, 4096, 4096, 4352, 1.0f);

    // VT (B,D,S)
    transpose_v_split<<<2048, 256>>>(qkvh, qkvl, vth, vtl);

    // fused attention: S GEMM + softmax + PV -> g_O (64, 2048, 128) fp32
    flash_attn<<<dim3(16, 64, 1), 256, FLASH_SMEM>>>(qkvh, qkvl, vth, vtl, pO);

    // scrambled reshape -> X split
    permute_o_split<<<65536, 256>>>(pO, xh, xl);

    // out = X @ Wo^T + bo   (4096 x 4096 x 4096)
    gemm_split<<<dim3(32, 32, 1), 256, SMEM_TOTAL>>>(
        xh, xl, woh, wol, out, nullptr, nullptr, bo,
        4096, 4096, 4096, 4096, 1.0f);
}